// round 17
// baseline (speedup 1.0000x reference)
#include <cuda_runtime.h>
#include <cstdint>

#define BB  256
#define LL  512
#define DD  64
#define NID 10000
#define TROWS 8          // fixed table rows; counts >= 8 use the per-element direct path

// dynamic smem layout (bytes):
//   [0      , 16384) W2s    : 64x64 f32
//   [16384  , 18432) table  : 8x64 f32   (g(a) rows, a in [0,8))
//   [18432  , 20480) h_all  : 8x64 f32   (relu(a*w1+b1) rows)
//   [20480  , 22528) cs     : 512 u32 packed (src_cnt | dst_cnt<<16) per src pos
//   [22528  , 24576) cd     : 512 u32 per dst pos
//   [24576  , 64576) hist   : 10000 u32 (lo16 = count in src, hi16 = count in dst)
#define SMEM_BYTES 64576

// Direct computation of g(a)[e..e+3] for the (never-in-practice) case a >= TROWS.
__device__ __forceinline__ float4 g_direct(uint32_t a, int lane,
                                           const float* __restrict__ W1,
                                           const float* __restrict__ b1,
                                           const float* __restrict__ b2,
                                           const float* __restrict__ W2s) {
    float4 s = ((const float4*)b2)[lane];
    const int e = lane * 4;
    for (int d = 0; d < DD; ++d) {
        float hv = fmaf((float)a, W1[d], b1[d]);
        hv = hv > 0.f ? hv : 0.f;
        s.x = fmaf(hv, W2s[(e + 0) * DD + d], s.x);
        s.y = fmaf(hv, W2s[(e + 1) * DD + d], s.y);
        s.z = fmaf(hv, W2s[(e + 2) * DD + d], s.z);
        s.w = fmaf(hv, W2s[(e + 3) * DD + d], s.w);
    }
    return s;
}

__global__ void __launch_bounds__(512, 2) fused_encode(
        const int* __restrict__ src,
        const int* __restrict__ dst,
        const float* __restrict__ W1,
        const float* __restrict__ b1,
        const float* __restrict__ W2,
        const float* __restrict__ b2,
        float* __restrict__ out) {
    extern __shared__ unsigned char sraw[];
    float*    W2s   = (float*)(sraw);
    float*    table = (float*)(sraw + 16384);
    float*    h_all = (float*)(sraw + 18432);
    uint32_t* cs    = (uint32_t*)(sraw + 20480);
    uint32_t* cd    = (uint32_t*)(sraw + 22528);
    uint32_t* hist  = (uint32_t*)(sraw + 24576);

    const int t = threadIdx.x;
    const int b = blockIdx.x;

    // --- P0: zero histogram (128-bit), stage W2 into smem, load ids ---
    const uint4 z = make_uint4(0u, 0u, 0u, 0u);
    #pragma unroll
    for (int i = t; i < NID / 4; i += 512) ((uint4*)hist)[i] = z;
    #pragma unroll
    for (int i = t; i < (DD * DD) / 4; i += 512)
        ((float4*)W2s)[i] = ((const float4*)W2)[i];

    const int sid = src[b * LL + t];
    const int did = dst[b * LL + t];
    __syncthreads();

    // --- P1: packed dual histogram + (independent) h_all rows 0..7 ---
    atomicAdd(&hist[sid], 1u);
    atomicAdd(&hist[did], 0x10000u);
    {
        const int a = t >> 6, d = t & 63;       // one entry per thread
        const float hv = fmaf((float)a, W1[d], b1[d]);
        h_all[t] = hv > 0.f ? hv : 0.f;
    }
    __syncthreads();

    // --- P2: table rows 0..7 (one entry per thread) + gather counts ---
    {
        const int a = t >> 6, e = t & 63;
        float s = b2[e];
        const float* hr = h_all + a * DD;
        const float* wr = W2s + e * DD;
        #pragma unroll 16
        for (int d = 0; d < DD; ++d) s = fmaf(hr[d], wr[d], s);
        table[t] = s;
    }
    const uint32_t hs = sid ? hist[sid] : 0u;   // padding id 0 -> (0,0)
    const uint32_t hd = did ? hist[did] : 0u;
    cs[t] = hs;
    cd[t] = hd;
    __syncthreads();

    // --- P3: streamed, float4-coalesced output (champion store loop,
    // nrows fixed at TROWS). 16 lanes per 64-f row, 16 iters for L=512. ---
    const int lane = t & 15;
    const float4* T4 = (const float4*)table;
    float4* __restrict__ osrc = (float4*)(out + (size_t)b * LL * DD);
    float4* __restrict__ odst = (float4*)(out + (size_t)BB * LL * DD
                                              + (size_t)b * LL * DD);

    for (int r = (t >> 4); r < LL; r += 32) {
        uint32_t c = cs[r];
        uint32_t a0 = c & 0xFFFFu, a1 = c >> 16;
        float4 v0 = (a0 < (uint32_t)TROWS) ? T4[a0 * 16 + lane]
                                           : g_direct(a0, lane, W1, b1, b2, W2s);
        float4 v1 = (a1 < (uint32_t)TROWS) ? T4[a1 * 16 + lane]
                                           : g_direct(a1, lane, W1, b1, b2, W2s);
        float4 w;
        w.x = v0.x + v1.x; w.y = v0.y + v1.y;
        w.z = v0.z + v1.z; w.w = v0.w + v1.w;
        osrc[r * 16 + lane] = w;

        c = cd[r];
        a0 = c & 0xFFFFu; a1 = c >> 16;
        v0 = (a0 < (uint32_t)TROWS) ? T4[a0 * 16 + lane]
                                    : g_direct(a0, lane, W1, b1, b2, W2s);
        v1 = (a1 < (uint32_t)TROWS) ? T4[a1 * 16 + lane]
                                    : g_direct(a1, lane, W1, b1, b2, W2s);
        w.x = v0.x + v1.x; w.y = v0.y + v1.y;
        w.z = v0.z + v1.z; w.w = v0.w + v1.w;
        odst[r * 16 + lane] = w;
    }
}

extern "C" void kernel_launch(void* const* d_in, const int* in_sizes, int n_in,
                              void* d_out, int out_size) {
    const int*   src = (const int*)d_in[0];
    const int*   dst = (const int*)d_in[1];
    const float* W1  = (const float*)d_in[2];
    const float* b1  = (const float*)d_in[3];
    const float* W2  = (const float*)d_in[4];
    const float* b2  = (const float*)d_in[5];
    float* out = (float*)d_out;

    cudaFuncSetAttribute(fused_encode,
                         cudaFuncAttributeMaxDynamicSharedMemorySize, SMEM_BYTES);
    fused_encode<<<BB, 512, SMEM_BYTES>>>(src, dst, W1, b1, W2, b2, out);
}